// round 16
// baseline (speedup 1.0000x reference)
#include <cuda_runtime.h>

// TypeAttention reduces algebraically to alpha[e] = 1 / in_degree(dst[e]) per
// relation (per-dst softmax over identical logits = uniform). Output = concat.
//
// SINGLE persistent kernel, all 977 blocks co-resident (launch_bounds(256,8)
// -> 1184 slots >= 977), software grid barriers between phases:
//   P1: hist_ui REDs + zero cnt_iu + reset bar2
//   P2: gather_ui (__ldcg) + hist_iu REDs   <- disjoint pipes, overlaps
//   P3: gather_iu (__ldcg) + zero cnt_ui + reset bar1
// Barrier counters self-reset (bar2 in P1 ordered by bar1; bar1 in P3 ordered
// by the launch boundary) -> state identical at every replay entry. Gather
// loads use __ldcg: REDs bypass L1 and zero-stores may allocate, so in-launch
// count reads must come from L2. Static zero-init covers the first call.

#define MAX_NODES 100000
#define TPB 256

__device__ int g_cnt[2 * MAX_NODES];   // [0,N): ui  [N,2N): iu
__device__ unsigned g_bar[2];          // barrier counters (self-resetting)

__device__ __forceinline__ void grid_bar(unsigned* ctr, unsigned nblocks) {
    __syncthreads();
    if (threadIdx.x == 0) {
        __threadfence();                        // publish REDs/stores
        unsigned old = atomicAdd(ctr, 1u);
        if (old + 1u < nblocks) {
            while (__ldcg((const unsigned*)ctr) < nblocks) __nanosleep(32);
        }
        __threadfence();                        // acquire
    }
    __syncthreads();
}

__global__ void __launch_bounds__(TPB, 8) fused_all(
    const int* __restrict__ dst_ui, const int* __restrict__ dst_iu,
    float* __restrict__ out, int E, int Nn, unsigned nblocks)
{
    const int i  = blockIdx.x * TPB + threadIdx.x;
    const int e4 = E >> 2;
    const bool act = i < e4;
    int4 a, b;
    if (act) {
        a = __ldg((const int4*)dst_ui + i);
        b = __ldg((const int4*)dst_iu + i);
    }

    // ── P1: hist_ui + zero cnt_iu + reset bar2 ──
    if (i == 0) g_bar[1] = 0;                   // visible before bar1 release
    if (i < Nn) g_cnt[MAX_NODES + i] = 0;       // ready cnt_iu for P2 REDs
    if (act) {
        atomicAdd(&g_cnt[a.x], 1);
        atomicAdd(&g_cnt[a.y], 1);
        atomicAdd(&g_cnt[a.z], 1);
        atomicAdd(&g_cnt[a.w], 1);
    } else if (i == e4) {
        for (int j = e4 << 2; j < E; j++) atomicAdd(&g_cnt[dst_ui[j]], 1);
    }
    grid_bar(&g_bar[0], nblocks);

    // ── P2: hist_iu REDs (fire-and-forget) + gather_ui ──
    if (act) {
        atomicAdd(&g_cnt[MAX_NODES + b.x], 1);
        atomicAdd(&g_cnt[MAX_NODES + b.y], 1);
        atomicAdd(&g_cnt[MAX_NODES + b.z], 1);
        atomicAdd(&g_cnt[MAX_NODES + b.w], 1);
        float4 r;
        r.x = 1.0f / (float)__ldcg(&g_cnt[a.x]);
        r.y = 1.0f / (float)__ldcg(&g_cnt[a.y]);
        r.z = 1.0f / (float)__ldcg(&g_cnt[a.z]);
        r.w = 1.0f / (float)__ldcg(&g_cnt[a.w]);
        ((float4*)out)[i] = r;
    } else if (i == e4) {
        for (int j = e4 << 2; j < E; j++) {
            atomicAdd(&g_cnt[MAX_NODES + dst_iu[j]], 1);
            out[j] = 1.0f / (float)__ldcg(&g_cnt[dst_ui[j]]);
        }
    }
    grid_bar(&g_bar[1], nblocks);

    // ── P3: gather_iu + zero cnt_ui (next replay) + reset bar1 ──
    if (i == 0) g_bar[0] = 0;                   // ordered by launch boundary
    if (i < Nn) g_cnt[i] = 0;
    if (act) {
        float4 r;
        r.x = 1.0f / (float)__ldcg(&g_cnt[MAX_NODES + b.x]);
        r.y = 1.0f / (float)__ldcg(&g_cnt[MAX_NODES + b.y]);
        r.z = 1.0f / (float)__ldcg(&g_cnt[MAX_NODES + b.z]);
        r.w = 1.0f / (float)__ldcg(&g_cnt[MAX_NODES + b.w]);
        ((float4*)(out + E))[i] = r;
    } else if (i == e4) {
        for (int j = e4 << 2; j < E; j++)
            out[E + j] = 1.0f / (float)__ldcg(&g_cnt[MAX_NODES + dst_iu[j]]);
    }
}

extern "C" void kernel_launch(void* const* d_in, const int* in_sizes, int n_in,
                              void* d_out, int out_size) {
    // Inputs: h_user, h_item, Wl_user, bl_user, Wl_item, bl_item,
    //         Wr_user, br_user, Wr_item, br_item, attn_w,
    //         src_ui, dst_ui, src_iu, dst_iu
    const int* dst_ui = (const int*)d_in[12];
    const int* dst_iu = (const int*)d_in[14];
    float* out = (float*)d_out;

    int D  = in_sizes[3];
    int Nn = in_sizes[0] / D;
    if (Nn > MAX_NODES) Nn = MAX_NODES;
    int E = in_sizes[12];

    int e4_threads = (E >> 2) + 1;                     // +1 for the tail
    int nthreads = e4_threads > Nn ? e4_threads : Nn;  // cover zeroing too
    unsigned eb = (nthreads + TPB - 1) / TPB;          // 977 <= 1184 resident

    fused_all<<<eb, TPB>>>(dst_ui, dst_iu, out, E, Nn, eb);
}